// round 6
// baseline (speedup 1.0000x reference)
#include <cuda_runtime.h>
#include <cuda_bf16.h>
#include <math.h>
#include <stdint.h>

#define BB 8
#define LL 2048
#define MM 2048
#define DD 256
#define OD 1024

// ---------------------------------------------------------------------------
// Scratch (device globals)
// ---------------------------------------------------------------------------
__device__ unsigned int g_p[(size_t)BB * LL * MM];            // packed p hi/lo bf16, 134 MB
__device__ __nv_bfloat16 g_xs_hi[BB*LL*DD],  g_xs_lo[BB*LL*DD];
__device__ __nv_bfloat16 g_mem_hi[BB*MM*DD], g_mem_lo[BB*MM*DD];
__device__ float g_indot[BB*LL], g_mbias[BB*MM];
__device__ float g_pmax[BB*LL*16], g_psum[BB*LL*16];
__device__ float g_pscale[BB*LL*16];
__device__ float g_rowmax[BB*LL];
__device__ float g_gmax[BB], g_Z[BB], g_o2part[BB*32*DD];

// ---------------------------------------------------------------------------
// PTX helpers
// ---------------------------------------------------------------------------
__device__ __forceinline__ uint32_t smem_u32(const void* p) {
    uint32_t a;
    asm("{ .reg .u64 t; cvta.to.shared.u64 t, %1; cvt.u32.u64 %0, t; }" : "=r"(a) : "l"(p));
    return a;
}
__device__ __forceinline__ void ldsm_x4(uint32_t* r, uint32_t a) {
    asm volatile("ldmatrix.sync.aligned.m8n8.x4.shared.b16 {%0,%1,%2,%3}, [%4];"
        : "=r"(r[0]), "=r"(r[1]), "=r"(r[2]), "=r"(r[3]) : "r"(a));
}
__device__ __forceinline__ void ldsm_x2(uint32_t* r, uint32_t a) {
    asm volatile("ldmatrix.sync.aligned.m8n8.x2.shared.b16 {%0,%1}, [%2];"
        : "=r"(r[0]), "=r"(r[1]) : "r"(a));
}
__device__ __forceinline__ void ldsm_x2t(uint32_t* r, uint32_t a) {
    asm volatile("ldmatrix.sync.aligned.m8n8.x2.trans.shared.b16 {%0,%1}, [%2];"
        : "=r"(r[0]), "=r"(r[1]) : "r"(a));
}
__device__ __forceinline__ void mma16816(float* d, const uint32_t* a, const uint32_t* b) {
    asm volatile("mma.sync.aligned.m16n8k16.row.col.f32.bf16.bf16.f32 "
        "{%0,%1,%2,%3}, {%4,%5,%6,%7}, {%8,%9}, {%0,%1,%2,%3};"
        : "+f"(d[0]), "+f"(d[1]), "+f"(d[2]), "+f"(d[3])
        : "r"(a[0]), "r"(a[1]), "r"(a[2]), "r"(a[3]), "r"(b[0]), "r"(b[1]));
}
__device__ __forceinline__ void split4(float4 v, uint2& hi, uint2& lo) {
    __nv_bfloat16 h0 = __float2bfloat16(v.x), h1 = __float2bfloat16(v.y);
    __nv_bfloat16 h2 = __float2bfloat16(v.z), h3 = __float2bfloat16(v.w);
    __nv_bfloat16 l0 = __float2bfloat16(v.x - __bfloat162float(h0));
    __nv_bfloat16 l1 = __float2bfloat16(v.y - __bfloat162float(h1));
    __nv_bfloat16 l2 = __float2bfloat16(v.z - __bfloat162float(h2));
    __nv_bfloat16 l3 = __float2bfloat16(v.w - __bfloat162float(h3));
    hi.x = (uint32_t)__bfloat16_as_ushort(h0) | ((uint32_t)__bfloat16_as_ushort(h1) << 16);
    hi.y = (uint32_t)__bfloat16_as_ushort(h2) | ((uint32_t)__bfloat16_as_ushort(h3) << 16);
    lo.x = (uint32_t)__bfloat16_as_ushort(l0) | ((uint32_t)__bfloat16_as_ushort(l1) << 16);
    lo.y = (uint32_t)__bfloat16_as_ushort(l2) | ((uint32_t)__bfloat16_as_ushort(l3) << 16);
}

// FFMA/ALU-only exp (no MUFU). Valid for x <= 0; rel err ~2e-6.
__device__ __forceinline__ float fast_exp(float x) {
    x = fmaxf(x, -80.0f);
    float y = x * 1.4426950408889634f;
    float nf = y + 12582912.0f;
    int   i  = __float_as_int(nf);
    float n  = nf - 12582912.0f;
    float f  = y - n;
    float p = 1.5403530e-4f;
    p = fmaf(p, f, 1.3333558e-3f);
    p = fmaf(p, f, 9.6181291e-3f);
    p = fmaf(p, f, 5.5504109e-2f);
    p = fmaf(p, f, 2.4022651e-1f);
    p = fmaf(p, f, 6.9314718e-1f);
    p = fmaf(p, f, 1.0f);
    return p * __int_as_float((i - 0x4B3FFF81) << 23);
}

__device__ __forceinline__ uint32_t packp(float p) {
    __nv_bfloat16 h = __float2bfloat16(p);
    __nv_bfloat16 l = __float2bfloat16(p - __bfloat162float(h));
    return (uint32_t)__bfloat16_as_ushort(h) | ((uint32_t)__bfloat16_as_ushort(l) << 16);
}
__device__ __forceinline__ float unpackp(uint32_t w) {
    return __uint_as_float(w << 16) + __uint_as_float(w & 0xFFFF0000u);
}

// ---------------------------------------------------------------------------
// smem layout (double-buffered operand tiles)
// ---------------------------------------------------------------------------
#define STRA  72
#define STRB2 264

#define G1_A_HI  0
#define G1_A_LO  18432
#define G1_B_HI  36864
#define G1_B_LO  55296
#define G1_BUFSZ 73728
#define G1_INDOT 147456
#define G1_MBIAS 147968
#define G1_PMAX  148480
#define G1_PSUM  149504
#define G1_SMEM  150528

#define G2_A_HI  0
#define G2_A_LO  9216
#define G2_B_HI  18432
#define G2_B_LO  52224
#define G2_BUFSZ 86016
#define G2_SCALE 172032
#define G2_SMEM  176128

// ---------------------------------------------------------------------------
// dots
// ---------------------------------------------------------------------------
__global__ void dots_kernel(const float* __restrict__ inp, const float* __restrict__ mem,
                            const float* __restrict__ mask, const float* __restrict__ wi,
                            const float* __restrict__ wm) {
    int row = blockIdx.x * 8 + (threadIdx.x >> 5);
    int lane = threadIdx.x & 31;
    bool isMem = row >= BB * LL;
    int r = isMem ? row - BB * LL : row;
    const float* src = (isMem ? mem : inp) + (size_t)r * DD;
    const float* w = isMem ? wm : wi;
    float s = 0.f;
    #pragma unroll
    for (int k = 0; k < 8; k++) { int d = lane + 32 * k; s = fmaf(src[d], w[d], s); }
    #pragma unroll
    for (int o = 16; o; o >>= 1) s += __shfl_xor_sync(0xffffffffu, s, o);
    if (lane == 0) {
        if (isMem) g_mbias[r] = s - 1e30f * (1.0f - mask[r]);
        else       g_indot[r] = s;
    }
}

// ---------------------------------------------------------------------------
// conv: hi/lo bf16 split of xs = input*ds and memory
// ---------------------------------------------------------------------------
__global__ void conv_kernel(const float* __restrict__ inp, const float* __restrict__ mem,
                            const float* __restrict__ ds) {
    const int N4 = BB * LL * DD / 4;
    int i = blockIdx.x * 256 + threadIdx.x;
    bool isMem = i >= N4;
    int j = isMem ? i - N4 : i;
    float4 x = ((const float4*)(isMem ? mem : inp))[j];
    if (!isMem) {
        float4 s = ((const float4*)ds)[j & (DD / 4 - 1)];
        x.x *= s.x; x.y *= s.y; x.z *= s.z; x.w *= s.w;
    }
    uint2 hv, lv;
    split4(x, hv, lv);
    ((uint2*)(isMem ? g_mem_hi : g_xs_hi))[j] = hv;
    ((uint2*)(isMem ? g_mem_lo : g_xs_lo))[j] = lv;
}

// ---------------------------------------------------------------------------
// GEMM1: s = xs.mem^T + indot + mbias; store p = exp(s - tile_max) packed bf16;
// per-(row,tile) max and sumexp. grid (L/128, M/128, B). Double-buffered.
// ---------------------------------------------------------------------------
__global__ void __launch_bounds__(256) gemm1_kernel() {
    extern __shared__ char sm[];
    const uint32_t s0 = smem_u32(sm);
    const int tid = threadIdx.x, lane = tid & 31, warp = tid >> 5;
    const int lbase = blockIdx.x * 128, nbase = blockIdx.y * 128, b = blockIdx.z;

    float* sIndot = (float*)(sm + G1_INDOT);
    float* sMbias = (float*)(sm + G1_MBIAS);
    if (tid < 128) {
        sIndot[tid] = g_indot[b * LL + lbase + tid];
        sMbias[tid] = g_mbias[b * MM + nbase + tid];
    }

    float acc[2][8][4];
    #pragma unroll
    for (int mt = 0; mt < 2; mt++)
        #pragma unroll
        for (int nt = 0; nt < 8; nt++)
            #pragma unroll
            for (int q = 0; q < 4; q++) acc[mt][nt][q] = 0.f;

    const int warpM = (warp >> 1) * 32, warpN = (warp & 1) * 64;
    const int g = lane >> 3, lr = lane & 7, h = (lane >> 3) & 1;

    uint4 sah[4], sal[4], sbh[4], sbl[4];

    auto LDG_CHUNK = [&](int kc) {
        int kk = kc * 64;
        #pragma unroll
        for (int j = 0; j < 4; j++) {
            int idx = tid + j * 256, row = idx >> 3, c8 = (idx & 7) * 8;
            size_t ra = (size_t)(b * LL + lbase + row) * DD + kk + c8;
            size_t rb = (size_t)(b * MM + nbase + row) * DD + kk + c8;
            sah[j] = *(const uint4*)(g_xs_hi + ra);  sal[j] = *(const uint4*)(g_xs_lo + ra);
            sbh[j] = *(const uint4*)(g_mem_hi + rb); sbl[j] = *(const uint4*)(g_mem_lo + rb);
        }
    };
    auto STS_CHUNK = [&](int buf) {
        uint32_t bb = (uint32_t)buf * G1_BUFSZ;
        #pragma unroll
        for (int j = 0; j < 4; j++) {
            int idx = tid + j * 256, row = idx >> 3, c8 = (idx & 7) * 8;
            uint32_t o = (uint32_t)(row * STRA + c8) * 2 + bb;
            *(uint4*)(sm + G1_A_HI + o) = sah[j];
            *(uint4*)(sm + G1_A_LO + o) = sal[j];
            *(uint4*)(sm + G1_B_HI + o) = sbh[j];
            *(uint4*)(sm + G1_B_LO + o) = sbl[j];
        }
    };

    LDG_CHUNK(0);
    STS_CHUNK(0);
    LDG_CHUNK(1);
    __syncthreads();

    for (int kc = 0; kc < 4; kc++) {
        if (kc < 3) STS_CHUNK((kc + 1) & 1);
        if (kc < 2) LDG_CHUNK(kc + 2);
        uint32_t bb = (uint32_t)(kc & 1) * G1_BUFSZ;
        #pragma unroll
        for (int ks = 0; ks < 4; ks++) {
            uint32_t aoff = s0 + bb + 2u * ((warpM + (g & 1) * 8 + lr) * STRA + ks * 16 + (g >> 1) * 8);
            uint32_t boff = s0 + bb + 2u * ((warpN + lr) * STRA + ks * 16 + h * 8);
            uint32_t ah[2][4], al[2][4], bh[8][2], bl[8][2];
            ldsm_x4(ah[0], aoff + G1_A_HI);
            ldsm_x4(ah[1], aoff + G1_A_HI + 16 * STRA * 2);
            #pragma unroll
            for (int nt = 0; nt < 8; nt++) ldsm_x2(bh[nt], boff + G1_B_HI + nt * 8 * STRA * 2);
            #pragma unroll
            for (int mt = 0; mt < 2; mt++)
                #pragma unroll
                for (int nt = 0; nt < 8; nt++) mma16816(acc[mt][nt], ah[mt], bh[nt]);
            #pragma unroll
            for (int nt = 0; nt < 8; nt++) ldsm_x2(bl[nt], boff + G1_B_LO + nt * 8 * STRA * 2);
            #pragma unroll
            for (int mt = 0; mt < 2; mt++)
                #pragma unroll
                for (int nt = 0; nt < 8; nt++) mma16816(acc[mt][nt], ah[mt], bl[nt]);
            ldsm_x4(al[0], aoff + G1_A_LO);
            ldsm_x4(al[1], aoff + G1_A_LO + 16 * STRA * 2);
            #pragma unroll
            for (int mt = 0; mt < 2; mt++)
                #pragma unroll
                for (int nt = 0; nt < 8; nt++) mma16816(acc[mt][nt], al[mt], bh[nt]);
        }
        __syncthreads();
    }

    // ---------- epilogue: biases, tile max, p store, sums ----------
    const int r0 = lane >> 2, c0 = 2 * (lane & 3);
    #pragma unroll
    for (int mt = 0; mt < 2; mt++)
        #pragma unroll
        for (int nt = 0; nt < 8; nt++) {
            int lrow = warpM + mt * 16 + r0;
            int lcol = warpN + nt * 8 + c0;
            float bi0 = sMbias[lcol], bi1 = sMbias[lcol + 1];
            acc[mt][nt][0] += sIndot[lrow] + bi0;
            acc[mt][nt][1] += sIndot[lrow] + bi1;
            acc[mt][nt][2] += sIndot[lrow + 8] + bi0;
            acc[mt][nt][3] += sIndot[lrow + 8] + bi1;
        }

    float pm[2][2];
    #pragma unroll
    for (int mt = 0; mt < 2; mt++) {
        pm[mt][0] = -INFINITY; pm[mt][1] = -INFINITY;
        #pragma unroll
        for (int nt = 0; nt < 8; nt++) {
            pm[mt][0] = fmaxf(pm[mt][0], fmaxf(acc[mt][nt][0], acc[mt][nt][1]));
            pm[mt][1] = fmaxf(pm[mt][1], fmaxf(acc[mt][nt][2], acc[mt][nt][3]));
        }
    }
    #pragma unroll
    for (int x = 1; x <= 2; x <<= 1)
        #pragma unroll
        for (int mt = 0; mt < 2; mt++)
            #pragma unroll
            for (int hf = 0; hf < 2; hf++)
                pm[mt][hf] = fmaxf(pm[mt][hf], __shfl_xor_sync(0xffffffffu, pm[mt][hf], x));

    float* sPm = (float*)(sm + G1_PMAX);
    float* sPz = (float*)(sm + G1_PSUM);
    int wn = warpN >> 6;
    if ((lane & 3) == 0) {
        #pragma unroll
        for (int mt = 0; mt < 2; mt++)
            #pragma unroll
            for (int hf = 0; hf < 2; hf++) {
                int row = warpM + mt * 16 + (lane >> 2) + hf * 8;
                sPm[row * 2 + wn] = pm[mt][hf];
            }
    }
    __syncthreads();

    float tm[2][2];
    #pragma unroll
    for (int mt = 0; mt < 2; mt++)
        #pragma unroll
        for (int hf = 0; hf < 2; hf++) {
            int row = warpM + mt * 16 + r0 + hf * 8;
            tm[mt][hf] = fmaxf(sPm[row * 2], sPm[row * 2 + 1]);
        }

    float pz[2][2] = {{0.f, 0.f}, {0.f, 0.f}};
    #pragma unroll
    for (int mt = 0; mt < 2; mt++) {
        #pragma unroll
        for (int nt = 0; nt < 8; nt++) {
            int lrow = warpM + mt * 16 + r0;
            int lcol = warpN + nt * 8 + c0;
            float p0 = fast_exp(acc[mt][nt][0] - tm[mt][0]);
            float p1 = fast_exp(acc[mt][nt][1] - tm[mt][0]);
            float p2 = fast_exp(acc[mt][nt][2] - tm[mt][1]);
            float p3 = fast_exp(acc[mt][nt][3] - tm[mt][1]);
            pz[mt][0] += p0 + p1;
            pz[mt][1] += p2 + p3;
            size_t base = ((size_t)(b * LL + lbase + lrow)) * MM + nbase + lcol;
            *(uint2*)(g_p + base)          = make_uint2(packp(p0), packp(p1));
            *(uint2*)(g_p + base + 8 * MM) = make_uint2(packp(p2), packp(p3));
        }
    }
    #pragma unroll
    for (int x = 1; x <= 2; x <<= 1)
        #pragma unroll
        for (int mt = 0; mt < 2; mt++)
            #pragma unroll
            for (int hf = 0; hf < 2; hf++)
                pz[mt][hf] += __shfl_xor_sync(0xffffffffu, pz[mt][hf], x);
    if ((lane & 3) == 0) {
        #pragma unroll
        for (int mt = 0; mt < 2; mt++)
            #pragma unroll
            for (int hf = 0; hf < 2; hf++) {
                int row = warpM + mt * 16 + (lane >> 2) + hf * 8;
                sPz[row * 2 + wn] = pz[mt][hf];
            }
    }
    __syncthreads();
    if (tid < 128) {
        float m = fmaxf(sPm[tid * 2], sPm[tid * 2 + 1]);
        float z = sPz[tid * 2] + sPz[tid * 2 + 1];
        size_t o = (size_t)(b * LL + lbase + tid) * 16 + blockIdx.y;
        g_pmax[o] = m; g_psum[o] = z;
    }
}

// ---------------------------------------------------------------------------
// combine: per row: global max, 1/Z, per-tile rescale factors
// ---------------------------------------------------------------------------
__global__ void combine_kernel() {
    int row = blockIdx.x * 256 + threadIdx.x;
    const float* pm = g_pmax + (size_t)row * 16;
    const float* pz = g_psum + (size_t)row * 16;
    float m = -INFINITY;
    #pragma unroll
    for (int t = 0; t < 16; t++) m = fmaxf(m, pm[t]);
    float z = 0.f;
    #pragma unroll
    for (int t = 0; t < 16; t++) z += pz[t] * fast_exp(pm[t] - m);
    float inv = 1.0f / z;
    g_rowmax[row] = m;
    #pragma unroll
    for (int t = 0; t < 16; t++)
        g_pscale[(size_t)row * 16 + t] = fast_exp(pm[t] - m) * inv;
}

// ---------------------------------------------------------------------------
// GEMM2: output_one = (p * scale) . mem. grid (L/64, B). Double-buffered.
// ---------------------------------------------------------------------------
__global__ void __launch_bounds__(256) gemm2_kernel(const float* __restrict__ inp,
                                                    float* __restrict__ out) {
    extern __shared__ char sm[];
    const uint32_t s0 = smem_u32(sm);
    const int tid = threadIdx.x, lane = tid & 31, warp = tid >> 5;
    const int lbase = blockIdx.x * 64, b = blockIdx.y;

    float* sScale = (float*)(sm + G2_SCALE);
    for (int i = tid; i < 64 * 16; i += 256)
        sScale[i] = g_pscale[(size_t)(b * LL + lbase + (i >> 4)) * 16 + (i & 15)];

    float acc[2][8][4];
    #pragma unroll
    for (int mt = 0; mt < 2; mt++)
        #pragma unroll
        for (int nt = 0; nt < 8; nt++)
            #pragma unroll
            for (int q = 0; q < 4; q++) acc[mt][nt][q] = 0.f;

    const int warpM = (warp >> 2) * 32, warpN = (warp & 3) * 64;
    const int g = lane >> 3, lr = lane & 7, h = (lane >> 3) & 1;
    const unsigned int* pBase = g_p + ((size_t)(b * LL + lbase)) * MM;
    const size_t memRow = (size_t)b * MM * DD;

    uint4 sa[4];
    uint4 sbh[8], sbl[8];

    auto LDG_CHUNK = [&](int kc) {
        int kk = kc * 64;
        #pragma unroll
        for (int j = 0; j < 4; j++) {
            int idx = tid + j * 256, row = idx >> 4, c4 = (idx & 15) * 4;
            sa[j] = *(const uint4*)(pBase + (size_t)row * MM + kk + c4);
        }
        #pragma unroll
        for (int j = 0; j < 8; j++) {
            int idx = tid + j * 256, row = idx >> 5, c = (idx & 31) * 8;
            size_t rb = memRow + (size_t)(kk + row) * DD + c;
            sbh[j] = *(const uint4*)(g_mem_hi + rb);
            sbl[j] = *(const uint4*)(g_mem_lo + rb);
        }
    };
    auto STS_CHUNK = [&](int kc) {
        uint32_t bb = (uint32_t)(kc & 1) * G2_BUFSZ;
        #pragma unroll
        for (int j = 0; j < 4; j++) {
            int idx = tid + j * 256, row = idx >> 4, c4 = (idx & 15) * 4;
            float sc = sScale[row * 16 + (kc >> 1)];
            uint4 u = sa[j];
            float4 v;
            v.x = unpackp(u.x) * sc;
            v.y = unpackp(u.y) * sc;
            v.z = unpackp(u.z) * sc;
            v.w = unpackp(u.w) * sc;
            uint2 hi, lo;
            split4(v, hi, lo);
            uint32_t o = (uint32_t)(row * STRA + c4) * 2 + bb;
            *(uint2*)(sm + G2_A_HI + o) = hi;
            *(uint2*)(sm + G2_A_LO + o) = lo;
        }
        #pragma unroll
        for (int j = 0; j < 8; j++) {
            int idx = tid + j * 256, row = idx >> 5, c = (idx & 31) * 8;
            uint32_t o = (uint32_t)(row * STRB2 + c) * 2 + bb;
            *(uint4*)(sm + G2_B_HI + o) = sbh[j];
            *(uint4*)(sm + G2_B_LO + o) = sbl[j];
        }
    };

    LDG_CHUNK(0);
    __syncthreads();   // sScale visible before STS uses it
    STS_CHUNK(0);
    LDG_CHUNK(1);
    __syncthreads();

    for (int kc = 0; kc < 32; kc++) {
        if (kc < 31) STS_CHUNK(kc + 1);
        if (kc < 30) LDG_CHUNK(kc + 2);
        uint32_t bb = (uint32_t)(kc & 1) * G2_BUFSZ;
        #pragma unroll
        for (int ks = 0; ks < 4; ks++) {
            uint32_t aoff = s0 + bb + 2u * ((warpM + (g & 1) * 8 + lr) * STRA + ks * 16 + (g >> 1) * 8);
            int kk = ks * 16 + h * 8 + lr;
            uint32_t boff = s0 + bb + 2u * (kk * STRB2 + warpN);
            uint32_t ah[2][4], al[2][4], bh[8][2], bl[8][2];
            ldsm_x4(ah[0], aoff + G2_A_HI);
            ldsm_x4(ah[1], aoff + G2_A_HI + 16 * STRA * 2);
            #pragma unroll
            for (int nt = 0; nt < 8; nt++) ldsm_x2t(bh[nt], boff + G2_B_HI + nt * 16);
            #pragma unroll
            for (int mt = 0; mt < 2; mt++)
                #pragma unroll
                for (int nt = 0; nt < 8; nt++) mma16816(acc[mt][nt], ah[mt], bh[nt]);
            #pragma unroll
            for (int nt = 0; nt < 8; nt++) ldsm_x2t(bl[nt], boff + G2_B_LO + nt * 16);
            #pragma unroll
            for (int mt = 0; mt < 2; mt++)
                #pragma unroll
                for (int nt = 0; nt < 8; nt++) mma16816(acc[mt][nt], ah[mt], bl[nt]);
            ldsm_x4(al[0], aoff + G2_A_LO);
            ldsm_x4(al[1], aoff + G2_A_LO + 16 * STRA * 2);
            #pragma unroll
            for (int mt = 0; mt < 2; mt++)
                #pragma unroll
                for (int nt = 0; nt < 8; nt++) mma16816(acc[mt][nt], al[mt], bh[nt]);
        }
        __syncthreads();
    }

    const int r0 = lane >> 2, c0 = 2 * (lane & 3);
    #pragma unroll
    for (int mt = 0; mt < 2; mt++) {
        #pragma unroll
        for (int nt = 0; nt < 8; nt++) {
            int lrow = warpM + mt * 16 + r0;
            int d = warpN + nt * 8 + c0;
            #pragma unroll
            for (int half = 0; half < 2; half++) {
                size_t grow = (size_t)(b * LL + lbase + lrow + half * 8);
                float2 xv = *(const float2*)(inp + grow * DD + d);
                float2 o1 = make_float2(acc[mt][nt][half * 2], acc[mt][nt][half * 2 + 1]);
                float* ob = out + grow * OD;
                *(float2*)(ob + d)          = xv;
                *(float2*)(ob + DD + d)     = o1;
                *(float2*)(ob + 2 * DD + d) = make_float2(xv.x * o1.x, xv.y * o1.y);
            }
        }
    }
}

// ---------------------------------------------------------------------------
// output_two path
// ---------------------------------------------------------------------------
__global__ void c0_kernel() {
    int b = blockIdx.x, tid = threadIdx.x;
    __shared__ float red[256];
    float m = -INFINITY;
    for (int l = tid; l < LL; l += 256) m = fmaxf(m, g_rowmax[b * LL + l]);
    red[tid] = m; __syncthreads();
    for (int s = 128; s; s >>= 1) { if (tid < s) red[tid] = fmaxf(red[tid], red[tid + s]); __syncthreads(); }
    float gmax = red[0]; __syncthreads();
    float z = 0.f;
    for (int l = tid; l < LL; l += 256) z += fast_exp(g_rowmax[b * LL + l] - gmax);
    red[tid] = z; __syncthreads();
    for (int s = 128; s; s >>= 1) { if (tid < s) red[tid] += red[tid + s]; __syncthreads(); }
    if (tid == 0) { g_gmax[b] = gmax; g_Z[b] = red[0]; }
}

__global__ void c1_kernel(const float* __restrict__ inp) {
    int b = blockIdx.y, sblk = blockIdx.x, tid = threadIdx.x;
    __shared__ float ws[64];
    int l0 = sblk * 64;
    if (tid < 64)
        ws[tid] = fast_exp(g_rowmax[b * LL + l0 + tid] - g_gmax[b]) * (1.0f / g_Z[b]);
    __syncthreads();
    float acc = 0.f;
    const float* xp = inp + ((size_t)b * LL + l0) * DD + tid;
    #pragma unroll 4
    for (int l = 0; l < 64; l++) acc = fmaf(ws[l], xp[(size_t)l * DD], acc);
    g_o2part[(b * 32 + sblk) * DD + tid] = acc;
}

__global__ void c2_kernel(float* __restrict__ out) {
    int b = blockIdx.y, tid = threadIdx.x;
    __shared__ float o2s[256];
    float a = 0.f;
    #pragma unroll
    for (int s = 0; s < 32; s++) a += g_o2part[(b * 32 + s) * DD + tid];
    o2s[tid] = a; __syncthreads();
    int lbase = blockIdx.x * 16;
    for (int rr = 0; rr < 16; rr++) {
        size_t ob = ((size_t)(b * LL + lbase + rr)) * OD;
        out[ob + 3 * DD + tid] = o2s[tid] * out[ob + DD + tid];
    }
}

// ---------------------------------------------------------------------------
extern "C" void kernel_launch(void* const* d_in, const int* in_sizes, int n_in,
                              void* d_out, int out_size) {
    const float* inp  = (const float*)d_in[0];
    const float* mem  = (const float*)d_in[1];
    const float* mask = (const float*)d_in[2];
    const float* wi   = (const float*)d_in[3];
    const float* wm   = (const float*)d_in[4];
    const float* ds   = (const float*)d_in[5];
    float* out = (float*)d_out;

    cudaFuncSetAttribute(gemm1_kernel, cudaFuncAttributeMaxDynamicSharedMemorySize, G1_SMEM);
    cudaFuncSetAttribute(gemm2_kernel, cudaFuncAttributeMaxDynamicSharedMemorySize, G2_SMEM);

    dots_kernel<<<(BB * (LL + MM)) / 8, 256>>>(inp, mem, mask, wi, wm);
    conv_kernel<<<2 * (BB * LL * DD / 4) / 256, 256>>>(inp, mem, ds);
    gemm1_kernel<<<dim3(LL / 128, MM / 128, BB), 256, G1_SMEM>>>();
    combine_kernel<<<BB * LL / 256, 256>>>();
    gemm2_kernel<<<dim3(LL / 64, BB), 256, G2_SMEM>>>(inp, out);
    c0_kernel<<<BB, 256>>>();
    c1_kernel<<<dim3(LL / 64, BB), 256>>>(inp);
    c2_kernel<<<dim3(LL / 16, BB), 256>>>(out);
}

// round 7
// speedup vs baseline: 1.4166x; 1.4166x over previous
#include <cuda_runtime.h>
#include <cuda_bf16.h>
#include <math.h>
#include <stdint.h>

#define BB 8
#define LL 2048
#define MM 2048
#define DD 256
#define OD 1024

#define LT 128      // CTA L rows
#define MT 32       // M tile
#define NTILES 64   // MM / MT

// ---------------------------------------------------------------------------
// Scratch (device globals)
// ---------------------------------------------------------------------------
__device__ __nv_bfloat16 g_xs_hi[BB*LL*DD],  g_xs_lo[BB*LL*DD];
__device__ __nv_bfloat16 g_mem_hi[BB*MM*DD], g_mem_lo[BB*MM*DD];
__device__ float g_indot[BB*LL], g_mbias[BB*MM];
__device__ float g_rowmax[BB*LL];
__device__ float g_gmax[BB], g_Z[BB], g_o2part[BB*32*DD];

// ---------------------------------------------------------------------------
// PTX helpers
// ---------------------------------------------------------------------------
__device__ __forceinline__ uint32_t smem_u32(const void* p) {
    uint32_t a;
    asm("{ .reg .u64 t; cvta.to.shared.u64 t, %1; cvt.u32.u64 %0, t; }" : "=r"(a) : "l"(p));
    return a;
}
__device__ __forceinline__ void ldsm_x4(uint32_t* r, uint32_t a) {
    asm volatile("ldmatrix.sync.aligned.m8n8.x4.shared.b16 {%0,%1,%2,%3}, [%4];"
        : "=r"(r[0]), "=r"(r[1]), "=r"(r[2]), "=r"(r[3]) : "r"(a));
}
__device__ __forceinline__ void ldsm_x2(uint32_t* r, uint32_t a) {
    asm volatile("ldmatrix.sync.aligned.m8n8.x2.shared.b16 {%0,%1}, [%2];"
        : "=r"(r[0]), "=r"(r[1]) : "r"(a));
}
__device__ __forceinline__ void ldsm_x2t(uint32_t* r, uint32_t a) {
    asm volatile("ldmatrix.sync.aligned.m8n8.x2.trans.shared.b16 {%0,%1}, [%2];"
        : "=r"(r[0]), "=r"(r[1]) : "r"(a));
}
__device__ __forceinline__ void mma16816(float* d, const uint32_t* a, const uint32_t* b) {
    asm volatile("mma.sync.aligned.m16n8k16.row.col.f32.bf16.bf16.f32 "
        "{%0,%1,%2,%3}, {%4,%5,%6,%7}, {%8,%9}, {%0,%1,%2,%3};"
        : "+f"(d[0]), "+f"(d[1]), "+f"(d[2]), "+f"(d[3])
        : "r"(a[0]), "r"(a[1]), "r"(a[2]), "r"(a[3]), "r"(b[0]), "r"(b[1]));
}
__device__ __forceinline__ void split4(float4 v, uint2& hi, uint2& lo) {
    __nv_bfloat16 h0 = __float2bfloat16(v.x), h1 = __float2bfloat16(v.y);
    __nv_bfloat16 h2 = __float2bfloat16(v.z), h3 = __float2bfloat16(v.w);
    __nv_bfloat16 l0 = __float2bfloat16(v.x - __bfloat162float(h0));
    __nv_bfloat16 l1 = __float2bfloat16(v.y - __bfloat162float(h1));
    __nv_bfloat16 l2 = __float2bfloat16(v.z - __bfloat162float(h2));
    __nv_bfloat16 l3 = __float2bfloat16(v.w - __bfloat162float(h3));
    hi.x = (uint32_t)__bfloat16_as_ushort(h0) | ((uint32_t)__bfloat16_as_ushort(h1) << 16);
    hi.y = (uint32_t)__bfloat16_as_ushort(h2) | ((uint32_t)__bfloat16_as_ushort(h3) << 16);
    lo.x = (uint32_t)__bfloat16_as_ushort(l0) | ((uint32_t)__bfloat16_as_ushort(l1) << 16);
    lo.y = (uint32_t)__bfloat16_as_ushort(l2) | ((uint32_t)__bfloat16_as_ushort(l3) << 16);
}
__device__ __forceinline__ void packpair(float x, float y, uint32_t& hi, uint32_t& lo) {
    __nv_bfloat16 hx = __float2bfloat16(x), hy = __float2bfloat16(y);
    __nv_bfloat16 lx = __float2bfloat16(x - __bfloat162float(hx));
    __nv_bfloat16 ly = __float2bfloat16(y - __bfloat162float(hy));
    hi = (uint32_t)__bfloat16_as_ushort(hx) | ((uint32_t)__bfloat16_as_ushort(hy) << 16);
    lo = (uint32_t)__bfloat16_as_ushort(lx) | ((uint32_t)__bfloat16_as_ushort(ly) << 16);
}
// FFMA/ALU-only exp for aux kernels
__device__ __forceinline__ float fast_exp(float x) {
    x = fmaxf(x, -80.0f);
    float y = x * 1.4426950408889634f;
    float nf = y + 12582912.0f;
    int   i  = __float_as_int(nf);
    float n  = nf - 12582912.0f;
    float f  = y - n;
    float p = 1.5403530e-4f;
    p = fmaf(p, f, 1.3333558e-3f);
    p = fmaf(p, f, 9.6181291e-3f);
    p = fmaf(p, f, 5.5504109e-2f);
    p = fmaf(p, f, 2.4022651e-1f);
    p = fmaf(p, f, 6.9314718e-1f);
    p = fmaf(p, f, 1.0f);
    return p * __int_as_float((i - 0x4B3FFF81) << 23);
}
__device__ __forceinline__ void cp_async16(uint32_t dst, const void* src) {
    asm volatile("cp.async.cg.shared.global [%0], [%1], 16;" :: "r"(dst), "l"(src) : "memory");
}
__device__ __forceinline__ void cp_commit() {
    asm volatile("cp.async.commit_group;" ::: "memory");
}
template <int N>
__device__ __forceinline__ void cp_wait() {
    asm volatile("cp.async.wait_group %0;" :: "n"(N) : "memory");
}

// ---------------------------------------------------------------------------
// smem layout (bytes)
// ---------------------------------------------------------------------------
#define SXS 264                 // row stride in halves
#define SX_HI  0                // 128 x 264 halves = 67584
#define SX_LO  67584
#define SM_B   135168           // mem tiles: 2 bufs x (hi 16896 + lo 16896)
#define SM_BUF 33792
#define SM_LOO 16896
#define SMB    202752           // mbias 2048 f32 = 8192
#define FUSED_SMEM 210944

// ---------------------------------------------------------------------------
// dots
// ---------------------------------------------------------------------------
__global__ void dots_kernel(const float* __restrict__ inp, const float* __restrict__ mem,
                            const float* __restrict__ mask, const float* __restrict__ wi,
                            const float* __restrict__ wm) {
    int row = blockIdx.x * 8 + (threadIdx.x >> 5);
    int lane = threadIdx.x & 31;
    bool isMem = row >= BB * LL;
    int r = isMem ? row - BB * LL : row;
    const float* src = (isMem ? mem : inp) + (size_t)r * DD;
    const float* w = isMem ? wm : wi;
    float s = 0.f;
    #pragma unroll
    for (int k = 0; k < 8; k++) { int d = lane + 32 * k; s = fmaf(src[d], w[d], s); }
    #pragma unroll
    for (int o = 16; o; o >>= 1) s += __shfl_xor_sync(0xffffffffu, s, o);
    if (lane == 0) {
        if (isMem) g_mbias[r] = s - 1e30f * (1.0f - mask[r]);
        else       g_indot[r] = s;
    }
}

// ---------------------------------------------------------------------------
// conv: hi/lo bf16 split of xs = input*ds and memory
// ---------------------------------------------------------------------------
__global__ void conv_kernel(const float* __restrict__ inp, const float* __restrict__ mem,
                            const float* __restrict__ ds) {
    const int N4 = BB * LL * DD / 4;
    int i = blockIdx.x * 256 + threadIdx.x;
    bool isMem = i >= N4;
    int j = isMem ? i - N4 : i;
    float4 x = ((const float4*)(isMem ? mem : inp))[j];
    if (!isMem) {
        float4 s = ((const float4*)ds)[j & (DD / 4 - 1)];
        x.x *= s.x; x.y *= s.y; x.z *= s.z; x.w *= s.w;
    }
    uint2 hv, lv;
    split4(x, hv, lv);
    ((uint2*)(isMem ? g_mem_hi : g_xs_hi))[j] = hv;
    ((uint2*)(isMem ? g_mem_lo : g_xs_lo))[j] = lv;
}

// ---------------------------------------------------------------------------
// FUSED: flash-style. CTA = 128 L-rows, loop 64 M-tiles of 32.
// 8 warps x 16 L-rows, full D=256 in accumulators.
// Writes out cols [0:768) and g_rowmax.
// ---------------------------------------------------------------------------
__global__ void __launch_bounds__(256, 1) fused_kernel(const float* __restrict__ inp,
                                                       float* __restrict__ out) {
    extern __shared__ char sm[];
    const uint32_t s0 = smem_u32(sm);
    const int tid = threadIdx.x, lane = tid & 31, warp = tid >> 5;
    const int lbase = blockIdx.x * LT, b = blockIdx.y;

    // ---- async prologue ----
    // xs hi/lo: 128 rows x 32 16B-chunks each
    #pragma unroll
    for (int j = 0; j < 16; j++) {
        int i = tid + j * 256;
        int row = i >> 5, c = i & 31;
        size_t src = (size_t)(b * LL + lbase + row) * DD + c * 8;
        uint32_t d = (uint32_t)(row * SXS + c * 8) * 2;
        cp_async16(s0 + SX_HI + d, g_xs_hi + src);
        cp_async16(s0 + SX_LO + d, g_xs_lo + src);
    }
    // mbias
    #pragma unroll
    for (int j = 0; j < 2; j++) {
        int i = tid + j * 256;
        cp_async16(s0 + SMB + i * 16, g_mbias + b * MM + i * 4);
    }
    auto LOADMEM = [&](int t, int buf) {
        uint32_t base = s0 + SM_B + (uint32_t)buf * SM_BUF;
        #pragma unroll
        for (int j = 0; j < 4; j++) {
            int i = tid + j * 256;
            int row = i >> 5, c = i & 31;
            size_t src = (size_t)(b * MM + t * MT + row) * DD + c * 8;
            uint32_t d = (uint32_t)(row * SXS + c * 8) * 2;
            cp_async16(base + d, g_mem_hi + src);
            cp_async16(base + SM_LOO + d, g_mem_lo + src);
        }
    };
    LOADMEM(0, 0);
    cp_commit();                 // group A: xs + mbias + tile0
    LOADMEM(1, 1);
    cp_commit();                 // group B: tile1
    cp_wait<1>();                // group A done
    __syncthreads();

    const int q = lane >> 3, lr = lane & 7, h = (lane >> 3) & 1;
    const int rr = lane >> 2, cc = (lane & 3) * 2;
    const int wl = warp * 16;
    const float idot0 = g_indot[b * LL + lbase + wl + rr];
    const float idot1 = g_indot[b * LL + lbase + wl + rr + 8];
    const float* smb = (const float*)(sm + SMB);

    float O[32][4];
    #pragma unroll
    for (int nt = 0; nt < 32; nt++) { O[nt][0] = 0.f; O[nt][1] = 0.f; O[nt][2] = 0.f; O[nt][3] = 0.f; }
    float m0 = -INFINITY, m1 = -INFINITY, z0 = 0.f, z1 = 0.f;

    for (int t = 0; t < NTILES; t++) {
        const uint32_t mh = s0 + SM_B + (uint32_t)(t & 1) * SM_BUF;
        const uint32_t mlo = mh + SM_LOO;

        // ---- S = xs . mem^T (3-pass bf16) ----
        float scf[4][4];
        #pragma unroll
        for (int nt = 0; nt < 4; nt++) { scf[nt][0]=0.f; scf[nt][1]=0.f; scf[nt][2]=0.f; scf[nt][3]=0.f; }
        #pragma unroll
        for (int ks = 0; ks < 16; ks++) {
            uint32_t ao = (uint32_t)((wl + (q & 1) * 8 + lr) * SXS + ks * 16 + (q >> 1) * 8) * 2;
            uint32_t ah[4], al[4];
            ldsm_x4(ah, s0 + SX_HI + ao);
            ldsm_x4(al, s0 + SX_LO + ao);
            uint32_t bh[4][2], bl[4][2];
            #pragma unroll
            for (int nt = 0; nt < 4; nt++) {
                uint32_t bo = (uint32_t)((nt * 8 + lr) * SXS + ks * 16 + h * 8) * 2;
                ldsm_x2(bh[nt], mh + bo);
                ldsm_x2(bl[nt], mlo + bo);
            }
            #pragma unroll
            for (int nt = 0; nt < 4; nt++) mma16816(scf[nt], ah, bh[nt]);
            #pragma unroll
            for (int nt = 0; nt < 4; nt++) mma16816(scf[nt], ah, bl[nt]);
            #pragma unroll
            for (int nt = 0; nt < 4; nt++) mma16816(scf[nt], al, bh[nt]);
        }

        // ---- bias + online softmax ----
        #pragma unroll
        for (int nt = 0; nt < 4; nt++) {
            int col = t * MT + nt * 8 + cc;
            float b0 = smb[col], b1 = smb[col + 1];
            scf[nt][0] += idot0 + b0; scf[nt][1] += idot0 + b1;
            scf[nt][2] += idot1 + b0; scf[nt][3] += idot1 + b1;
        }
        float tm0 = -INFINITY, tm1 = -INFINITY;
        #pragma unroll
        for (int nt = 0; nt < 4; nt++) {
            tm0 = fmaxf(tm0, fmaxf(scf[nt][0], scf[nt][1]));
            tm1 = fmaxf(tm1, fmaxf(scf[nt][2], scf[nt][3]));
        }
        #pragma unroll
        for (int x = 1; x <= 2; x <<= 1) {
            tm0 = fmaxf(tm0, __shfl_xor_sync(0xffffffffu, tm0, x));
            tm1 = fmaxf(tm1, __shfl_xor_sync(0xffffffffu, tm1, x));
        }
        float mn0 = fmaxf(m0, tm0), mn1 = fmaxf(m1, tm1);
        float sc0 = __expf(m0 - mn0), sc1 = __expf(m1 - mn1);
        m0 = mn0; m1 = mn1;
        float lz0 = 0.f, lz1 = 0.f;
        #pragma unroll
        for (int nt = 0; nt < 4; nt++) {
            scf[nt][0] = __expf(scf[nt][0] - m0);
            scf[nt][1] = __expf(scf[nt][1] - m0);
            scf[nt][2] = __expf(scf[nt][2] - m1);
            scf[nt][3] = __expf(scf[nt][3] - m1);
            lz0 += scf[nt][0] + scf[nt][1];
            lz1 += scf[nt][2] + scf[nt][3];
        }
        z0 = z0 * sc0 + lz0;
        z1 = z1 * sc1 + lz1;
        #pragma unroll
        for (int nt = 0; nt < 32; nt++) {
            O[nt][0] *= sc0; O[nt][1] *= sc0;
            O[nt][2] *= sc1; O[nt][3] *= sc1;
        }

        // ---- pack P into A-fragments (hi/lo) ----
        uint32_t ph[2][4], pl[2][4];
        #pragma unroll
        for (int j2 = 0; j2 < 2; j2++) {
            packpair(scf[2*j2][0],   scf[2*j2][1],   ph[j2][0], pl[j2][0]);
            packpair(scf[2*j2][2],   scf[2*j2][3],   ph[j2][1], pl[j2][1]);
            packpair(scf[2*j2+1][0], scf[2*j2+1][1], ph[j2][2], pl[j2][2]);
            packpair(scf[2*j2+1][2], scf[2*j2+1][3], ph[j2][3], pl[j2][3]);
        }

        // ---- PV: O += P . mem (3-pass) ----
        #pragma unroll
        for (int ks = 0; ks < 2; ks++) {
            #pragma unroll
            for (int nt = 0; nt < 32; nt++) {
                uint32_t bo = (uint32_t)((ks * 16 + h * 8 + lr) * SXS + nt * 8) * 2;
                uint32_t bh2[2], bl2[2];
                ldsm_x2t(bh2, mh + bo);
                ldsm_x2t(bl2, mlo + bo);
                mma16816(O[nt], ph[ks], bh2);
                mma16816(O[nt], ph[ks], bl2);
                mma16816(O[nt], pl[ks], bh2);
            }
        }

        __syncthreads();                     // all warps done with buf (t&1)
        if (t + 2 < NTILES) LOADMEM(t + 2, t & 1);
        cp_commit();
        cp_wait<1>();                        // tile t+1 ready
        __syncthreads();
    }

    // ---- epilogue ----
    #pragma unroll
    for (int x = 1; x <= 2; x <<= 1) {
        z0 += __shfl_xor_sync(0xffffffffu, z0, x);
        z1 += __shfl_xor_sync(0xffffffffu, z1, x);
    }
    float inv0 = 1.0f / z0, inv1 = 1.0f / z1;
    if ((lane & 3) == 0) {
        g_rowmax[b * LL + lbase + wl + rr] = m0;
        g_rowmax[b * LL + lbase + wl + rr + 8] = m1;
    }
    size_t grow0 = (size_t)(b * LL + lbase + wl + rr);
    size_t grow1 = grow0 + 8;
    float* ob0 = out + grow0 * OD;
    float* ob1 = out + grow1 * OD;
    const float* xi0 = inp + grow0 * DD;
    const float* xi1 = inp + grow1 * DD;
    #pragma unroll
    for (int nt = 0; nt < 32; nt++) {
        int d = nt * 8 + cc;
        float2 xv0 = *(const float2*)(xi0 + d);
        float2 xv1 = *(const float2*)(xi1 + d);
        float2 o0 = make_float2(O[nt][0] * inv0, O[nt][1] * inv0);
        float2 o1 = make_float2(O[nt][2] * inv1, O[nt][3] * inv1);
        *(float2*)(ob0 + d)          = xv0;
        *(float2*)(ob0 + DD + d)     = o0;
        *(float2*)(ob0 + 2 * DD + d) = make_float2(xv0.x * o0.x, xv0.y * o0.y);
        *(float2*)(ob1 + d)          = xv1;
        *(float2*)(ob1 + DD + d)     = o1;
        *(float2*)(ob1 + 2 * DD + d) = make_float2(xv1.x * o1.x, xv1.y * o1.y);
    }
}

// ---------------------------------------------------------------------------
// output_two path
// ---------------------------------------------------------------------------
__global__ void c0_kernel() {
    int b = blockIdx.x, tid = threadIdx.x;
    __shared__ float red[256];
    float m = -INFINITY;
    for (int l = tid; l < LL; l += 256) m = fmaxf(m, g_rowmax[b * LL + l]);
    red[tid] = m; __syncthreads();
    for (int s = 128; s; s >>= 1) { if (tid < s) red[tid] = fmaxf(red[tid], red[tid + s]); __syncthreads(); }
    float gmax = red[0]; __syncthreads();
    float z = 0.f;
    for (int l = tid; l < LL; l += 256) z += fast_exp(g_rowmax[b * LL + l] - gmax);
    red[tid] = z; __syncthreads();
    for (int s = 128; s; s >>= 1) { if (tid < s) red[tid] += red[tid + s]; __syncthreads(); }
    if (tid == 0) { g_gmax[b] = gmax; g_Z[b] = red[0]; }
}

__global__ void c1_kernel(const float* __restrict__ inp) {
    int b = blockIdx.y, sblk = blockIdx.x, tid = threadIdx.x;
    __shared__ float ws[64];
    int l0 = sblk * 64;
    if (tid < 64)
        ws[tid] = fast_exp(g_rowmax[b * LL + l0 + tid] - g_gmax[b]) * (1.0f / g_Z[b]);
    __syncthreads();
    float acc = 0.f;
    const float* xp = inp + ((size_t)b * LL + l0) * DD + tid;
    #pragma unroll 4
    for (int l = 0; l < 64; l++) acc = fmaf(ws[l], xp[(size_t)l * DD], acc);
    g_o2part[(b * 32 + sblk) * DD + tid] = acc;
}

__global__ void c2_kernel(float* __restrict__ out) {
    int b = blockIdx.y, tid = threadIdx.x;
    __shared__ float o2s[256];
    float a = 0.f;
    #pragma unroll
    for (int s = 0; s < 32; s++) a += g_o2part[(b * 32 + s) * DD + tid];
    o2s[tid] = a; __syncthreads();
    int lbase = blockIdx.x * 16;
    for (int rr = 0; rr < 16; rr++) {
        size_t ob = ((size_t)(b * LL + lbase + rr)) * OD;
        out[ob + 3 * DD + tid] = o2s[tid] * out[ob + DD + tid];
    }
}

// ---------------------------------------------------------------------------
extern "C" void kernel_launch(void* const* d_in, const int* in_sizes, int n_in,
                              void* d_out, int out_size) {
    const float* inp  = (const float*)d_in[0];
    const float* mem  = (const float*)d_in[1];
    const float* mask = (const float*)d_in[2];
    const float* wi   = (const float*)d_in[3];
    const float* wm   = (const float*)d_in[4];
    const float* ds   = (const float*)d_in[5];
    float* out = (float*)d_out;

    cudaFuncSetAttribute(fused_kernel, cudaFuncAttributeMaxDynamicSharedMemorySize, FUSED_SMEM);

    dots_kernel<<<(BB * (LL + MM)) / 8, 256>>>(inp, mem, mask, wi, wm);
    conv_kernel<<<2 * (BB * LL * DD / 4) / 256, 256>>>(inp, mem, ds);
    fused_kernel<<<dim3(LL / LT, BB), 256, FUSED_SMEM>>>(inp, out);
    c0_kernel<<<BB, 256>>>();
    c1_kernel<<<dim3(LL / 64, BB), 256>>>(inp);
    c2_kernel<<<dim3(LL / 16, BB), 256>>>(out);
}